// round 6
// baseline (speedup 1.0000x reference)
#include <cuda_runtime.h>
#include <cuda_bf16.h>
#include <cuda_fp16.h>
#include <cstdint>
#include <cstring>

#define N_NODES 12288
#define DIM 256
#define KCL 16
#define KS 512               // stored A cols (hi | lo)
#define KV 768               // virtual K
#define NIT (KV / 32)        // 24 k-chunks of 32
#define CAP 128              // per-node edge bucket capacity

// ---- static device scratch ----
__device__ __half g_t[N_NODES * DIM];                // GEMM output, fp16
__device__ __nv_bfloat16 g_abig[N_NODES * KS];       // [N,512] = [hi|lo]
__device__ __nv_bfloat16 g_wbig1[KV * DIM];          // [768,256] = [Whi; Whi; Wlo]
__device__ __nv_bfloat16 g_wbig2[KV * DIM];
__device__ int   g_deg[N_NODES];
__device__ int2  g_bucket[N_NODES * CAP];            // (src, bits(w))
__device__ float g_red[KCL + 1];                     // [0:16) colsumsq, [16] ticket

// ================= PTX helpers =================
__device__ __forceinline__ uint32_t smem_u32(const void* p) {
    uint32_t a;
    asm("{ .reg .u64 t; cvta.to.shared.u64 t, %1; cvt.u32.u64 %0, t; }" : "=r"(a) : "l"(p));
    return a;
}
#define CP_ASYNC16(sa, gp) \
    asm volatile("cp.async.cg.shared.global [%0], [%1], 16;" :: "r"(sa), "l"(gp))
#define CP_COMMIT() asm volatile("cp.async.commit_group;" ::: "memory")
#define CP_WAIT(n)  asm volatile("cp.async.wait_group %0;" :: "n"(n) : "memory")

#define LDSM4(r0, r1, r2, r3, a) \
    asm volatile("ldmatrix.sync.aligned.m8n8.x4.shared.b16 {%0,%1,%2,%3}, [%4];" \
                 : "=r"(r0), "=r"(r1), "=r"(r2), "=r"(r3) : "r"(a))
#define LDSM2T(r0, r1, a) \
    asm volatile("ldmatrix.sync.aligned.m8n8.x2.trans.shared.b16 {%0,%1}, [%2];" \
                 : "=r"(r0), "=r"(r1) : "r"(a))
#define MMA16816(c, a, b) \
    asm volatile("mma.sync.aligned.m16n8k16.row.col.f32.bf16.bf16.f32 " \
                 "{%0,%1,%2,%3}, {%4,%5,%6,%7}, {%8,%9}, {%0,%1,%2,%3};" \
                 : "+f"((c)[0]), "+f"((c)[1]), "+f"((c)[2]), "+f"((c)[3]) \
                 : "r"((a)[0]), "r"((a)[1]), "r"((a)[2]), "r"((a)[3]), \
                   "r"((b)[0]), "r"((b)[1]))

__device__ __forceinline__ uint32_t bf2_pack(float a, float b) {
    __nv_bfloat162 t = __halves2bfloat162(__float2bfloat16_rn(a), __float2bfloat16_rn(b));
    uint32_t u;
    memcpy(&u, &t, 4);
    return u;
}

// ================= mega prologue: bucket-fill + convW1 + convW2 + convA =================
__global__ __launch_bounds__(256) void k_mega(const int* __restrict__ src,
                                              const int* __restrict__ dst,
                                              const float* __restrict__ ew,
                                              const float* __restrict__ x,
                                              const float* __restrict__ W1,
                                              const float* __restrict__ W2,
                                              int FB) {
    int b = blockIdx.x, tid = threadIdx.x;
    if (b < FB) {
        int e = (b * 256 + tid) * 2;
        int2 s2 = *(const int2*)(src + e);
        int2 d2 = *(const int2*)(dst + e);
        float2 w2 = *(const float2*)(ew + e);
        int p = atomicAdd(&g_deg[d2.x], 1);
        if (p < CAP) g_bucket[(size_t)d2.x * CAP + p] = make_int2(s2.x, __float_as_int(w2.x));
        p = atomicAdd(&g_deg[d2.y], 1);
        if (p < CAP) g_bucket[(size_t)d2.y * CAP + p] = make_int2(s2.y, __float_as_int(w2.y));
    } else if (b < FB + 128) {
        int rel = b - FB;
        const float* W = (rel < 64) ? W1 : W2;
        __nv_bfloat16* Wt = (rel < 64) ? g_wbig1 : g_wbig2;
        int idx = ((rel & 63) * 256 + tid) * 4;
        float4 v = *(const float4*)(W + idx);
        int k = idx >> 8, n = idx & 255;
        float hx = __bfloat162float(__float2bfloat16_rn(v.x));
        float hy = __bfloat162float(__float2bfloat16_rn(v.y));
        float hz = __bfloat162float(__float2bfloat16_rn(v.z));
        float hw = __bfloat162float(__float2bfloat16_rn(v.w));
        uint2 hv = make_uint2(bf2_pack(v.x, v.y), bf2_pack(v.z, v.w));
        uint2 lv = make_uint2(bf2_pack(v.x - hx, v.y - hy), bf2_pack(v.z - hz, v.w - hw));
        *(uint2*)&Wt[(size_t)k * DIM + n]         = hv;
        *(uint2*)&Wt[(size_t)(k + 256) * DIM + n] = hv;
        *(uint2*)&Wt[(size_t)(k + 512) * DIM + n] = lv;
    } else {
        int idx = ((b - FB - 128) * 256 + tid) * 4;
        float4 v = *(const float4*)(x + idx);
        int m = idx >> 8, c = idx & 255;
        float hx = __bfloat162float(__float2bfloat16_rn(v.x));
        float hy = __bfloat162float(__float2bfloat16_rn(v.y));
        float hz = __bfloat162float(__float2bfloat16_rn(v.z));
        float hw = __bfloat162float(__float2bfloat16_rn(v.w));
        __nv_bfloat16* o = g_abig + (size_t)m * KS + c;
        *(uint2*)(o)       = make_uint2(bf2_pack(v.x, v.y), bf2_pack(v.z, v.w));
        *(uint2*)(o + 256) = make_uint2(bf2_pack(v.x - hx, v.y - hy), bf2_pack(v.z - hz, v.w - hw));
    }
}

// ================= mma.sync bf16 GEMM: t[12288,256](fp16) = split(A) @ split(W) =================
// BM=64, BN=64, BK=32, 128 threads (4 warps, 2x2), warp tile 32x32, 4-stage ring
#define APITCH 40
#define BPITCH 72
#define A_ST (64 * APITCH)
#define B_ST (32 * BPITCH)

__global__ __launch_bounds__(128, 5) void k_mma(const __nv_bfloat16* __restrict__ Ab,
                                                const __nv_bfloat16* __restrict__ Wb,
                                                __half* __restrict__ C) {
    __shared__ __align__(16) __nv_bfloat16 As[4 * A_ST];
    __shared__ __align__(16) __nv_bfloat16 Bs[4 * B_ST];
    int tid = threadIdx.x;
    int bm = blockIdx.y * 64, bn = blockIdx.x * 64;
    int warp = tid >> 5, lane = tid & 31;
    int wr = warp >> 1, wc = warp & 1;

    float acc[2][4][4];
#pragma unroll
    for (int i = 0; i < 2; i++)
#pragma unroll
        for (int j = 0; j < 4; j++)
#pragma unroll
            for (int f = 0; f < 4; f++) acc[i][j][f] = 0.f;

    // load mapping: A row=tid>>1, cols (tid&1)*16 (+0,+8); B row=tid>>2, cols (tid&3)*16 (+0,+8)
    int ar = tid >> 1, ac = (tid & 1) * 16;
    int br = tid >> 2, bc = (tid & 3) * 16;

    // hoisted smem store addresses (per slot: + slot*stride*2B)
    uint32_t sA0 = smem_u32(&As[ar * APITCH + ac]);
    uint32_t sB0 = smem_u32(&Bs[br * BPITCH + bc]);
    // hoisted ldmatrix base addresses
    uint32_t lA0 = smem_u32(&As[(wr * 32 + (lane & 15)) * APITCH + ((lane >> 4) << 3)]);
    uint32_t lB0 = smem_u32(&Bs[(lane & 15) * BPITCH + wc * 32]);

#define LOAD_TILE(i, slot)                                                           \
    do {                                                                             \
        int k0 = (i) * 32;                                                           \
        int ak0 = (k0 < 512) ? k0 : k0 - 512;                                        \
        const __nv_bfloat16* ga = Ab + (size_t)(bm + ar) * KS + ak0 + ac;            \
        const __nv_bfloat16* gb = Wb + (size_t)(k0 + br) * DIM + bn + bc;            \
        CP_ASYNC16(sA0 + (slot) * (A_ST * 2), ga);                                   \
        CP_ASYNC16(sA0 + (slot) * (A_ST * 2) + 16, ga + 8);                          \
        CP_ASYNC16(sB0 + (slot) * (B_ST * 2), gb);                                   \
        CP_ASYNC16(sB0 + (slot) * (B_ST * 2) + 16, gb + 8);                          \
    } while (0)

    LOAD_TILE(0, 0); CP_COMMIT();
    LOAD_TILE(1, 1); CP_COMMIT();
    LOAD_TILE(2, 2); CP_COMMIT();

    for (int i = 0; i < NIT; i++) {
        int slot = i & 3;
        CP_WAIT(2);
        __syncthreads();
        if (i + 3 < NIT) LOAD_TILE(i + 3, (i + 3) & 3);
        CP_COMMIT();
        uint32_t lA = lA0 + slot * (A_ST * 2);
        uint32_t lB = lB0 + slot * (B_ST * 2);
#pragma unroll
        for (int kt = 0; kt < 2; kt++) {
            uint32_t a[2][4];
#pragma unroll
            for (int mt = 0; mt < 2; mt++)
                LDSM4(a[mt][0], a[mt][1], a[mt][2], a[mt][3],
                      lA + (mt * 16 * APITCH + kt * 16) * 2);
            uint32_t b[4][2];
#pragma unroll
            for (int nt = 0; nt < 4; nt++)
                LDSM2T(b[nt][0], b[nt][1], lB + (kt * 16 * BPITCH + nt * 8) * 2);
#pragma unroll
            for (int mt = 0; mt < 2; mt++)
#pragma unroll
                for (int nt = 0; nt < 4; nt++) MMA16816(acc[mt][nt], a[mt], b[nt]);
        }
    }

#pragma unroll
    for (int mt = 0; mt < 2; mt++)
#pragma unroll
        for (int nt = 0; nt < 4; nt++) {
            int row = bm + wr * 32 + mt * 16 + (lane >> 2);
            int col = bn + wc * 32 + nt * 8 + (lane & 3) * 2;
            *(__half2*)&C[(size_t)row * DIM + col] =
                __floats2half2_rn(acc[mt][nt][0], acc[mt][nt][1]);
            *(__half2*)&C[(size_t)(row + 8) * DIM + col] =
                __floats2half2_rn(acc[mt][nt][2], acc[mt][nt][3]);
        }
}

// ================= gather core: warp-per-node, lane owns cols [8l, 8l+8), fp16 t =================
__device__ __forceinline__ void gather_node(const __half* __restrict__ t,
                                            const float* __restrict__ bias,
                                            int node, int lane,
                                            float4& a0, float4& a1) {
    a0 = *(const float4*)&bias[8 * lane];
    a1 = *(const float4*)&bias[8 * lane + 4];
    int cnt = min(g_deg[node], CAP);
    const int2* bk = g_bucket + (size_t)node * CAP;
    for (int j0 = 0; j0 < cnt; j0 += 32) {
        int2 e = make_int2(0, 0);
        if (j0 + lane < cnt) e = bk[j0 + lane];
        int m = min(32, cnt - j0);
#pragma unroll 4
        for (int j = 0; j < m; j++) {
            int s = __shfl_sync(0xffffffffu, e.x, j);
            float w = __int_as_float(__shfl_sync(0xffffffffu, e.y, j));
            uint4 v = *(const uint4*)(t + (size_t)s * DIM + 8 * lane);
            float2 f0 = __half22float2(*(__half2*)&v.x);
            float2 f1 = __half22float2(*(__half2*)&v.y);
            float2 f2 = __half22float2(*(__half2*)&v.z);
            float2 f3 = __half22float2(*(__half2*)&v.w);
            a0.x += w * f0.x; a0.y += w * f0.y; a0.z += w * f1.x; a0.w += w * f1.y;
            a1.x += w * f2.x; a1.y += w * f2.y; a1.z += w * f3.x; a1.w += w * f3.y;
        }
    }
    a0.x = fmaxf(a0.x, 0.f); a0.y = fmaxf(a0.y, 0.f);
    a0.z = fmaxf(a0.z, 0.f); a0.w = fmaxf(a0.w, 0.f);
    a1.x = fmaxf(a1.x, 0.f); a1.y = fmaxf(a1.y, 0.f);
    a1.z = fmaxf(a1.z, 0.f); a1.w = fmaxf(a1.w, 0.f);
}

// ================= agg layer 1: gather + relu -> bf16 hi/lo split =================
__global__ __launch_bounds__(256) void k_agg1(const __half* __restrict__ t,
                                              const float* __restrict__ bias,
                                              __nv_bfloat16* __restrict__ outs) {
    int warp = threadIdx.x >> 5, lane = threadIdx.x & 31;
    int node = blockIdx.x * 8 + warp;
    float4 a0, a1;
    gather_node(t, bias, node, lane, a0, a1);
    float hx = __bfloat162float(__float2bfloat16_rn(a0.x));
    float hy = __bfloat162float(__float2bfloat16_rn(a0.y));
    float hz = __bfloat162float(__float2bfloat16_rn(a0.z));
    float hw = __bfloat162float(__float2bfloat16_rn(a0.w));
    float gx = __bfloat162float(__float2bfloat16_rn(a1.x));
    float gy = __bfloat162float(__float2bfloat16_rn(a1.y));
    float gz = __bfloat162float(__float2bfloat16_rn(a1.z));
    float gw = __bfloat162float(__float2bfloat16_rn(a1.w));
    __nv_bfloat16* o = outs + (size_t)node * KS + 8 * lane;
    *(uint4*)(o) = make_uint4(bf2_pack(a0.x, a0.y), bf2_pack(a0.z, a0.w),
                              bf2_pack(a1.x, a1.y), bf2_pack(a1.z, a1.w));
    *(uint4*)(o + 256) = make_uint4(bf2_pack(a0.x - hx, a0.y - hy),
                                    bf2_pack(a0.z - hz, a0.w - hw),
                                    bf2_pack(a1.x - gx, a1.y - gy),
                                    bf2_pack(a1.z - gz, a1.w - gw));
}

// ================= fused agg2 + MLP + softmax + colsumsq + loss (ticket) =================
__global__ __launch_bounds__(512) void k_aggmlp(const __half* __restrict__ t,
                                                const float* __restrict__ bias,
                                                const float* __restrict__ Wm,
                                                const float* __restrict__ bm,
                                                float* __restrict__ out,
                                                float* __restrict__ out_loss, int Nn) {
    __shared__ float sW[KCL * DIM];
    __shared__ float sh[16][DIM];
    __shared__ float part[16][KCL];
    __shared__ float sbm[KCL];
    int tid = threadIdx.x;
    for (int idx = tid; idx < KCL * DIM; idx += 512)
        sW[idx] = Wm[(idx & 255) * KCL + (idx >> 8)];
    if (tid < KCL) sbm[tid] = bm[tid];

    int warp = tid >> 5, lane = tid & 31;
    int node = blockIdx.x * 16 + warp;
    float4 a0, a1;
    gather_node(t, bias, node, lane, a0, a1);
    *(float4*)&sh[warp][8 * lane] = a0;
    *(float4*)&sh[warp][8 * lane + 4] = a1;
    __syncthreads();

    float acc[KCL];
#pragma unroll
    for (int k = 0; k < KCL; k++) acc[k] = 0.f;
#pragma unroll
    for (int m = 0; m < 8; m++) {
        float hv = sh[warp][lane + 32 * m];
#pragma unroll
        for (int k = 0; k < KCL; k++) acc[k] += hv * sW[k * DIM + lane + 32 * m];
    }
#pragma unroll
    for (int off = 16; off >= 1; off >>= 1)
#pragma unroll
        for (int k = 0; k < KCL; k++) acc[k] += __shfl_xor_sync(0xffffffffu, acc[k], off);

    if (lane < KCL) {
        float logit = acc[lane] + sbm[lane];
        float mx = logit;
#pragma unroll
        for (int off = 8; off >= 1; off >>= 1) mx = fmaxf(mx, __shfl_xor_sync(0xffffu, mx, off));
        float e = expf(logit - mx);
        float se = e;
#pragma unroll
        for (int off = 8; off >= 1; off >>= 1) se += __shfl_xor_sync(0xffffu, se, off);
        float sv = e / se;
        out[(size_t)node * KCL + lane] = sv;
        part[warp][lane] = sv * sv;
    }
    __syncthreads();
    if (tid < KCL) {
        float s = 0.f;
#pragma unroll
        for (int w = 0; w < 16; w++) s += part[w][tid];
        atomicAdd(&g_red[tid], s);
    }
    __syncthreads();
    if (tid == 0) {
        __threadfence();
        int prev = atomicAdd((int*)&g_red[KCL], 1);
        if (prev == (int)gridDim.x - 1) {
            float L = 0.f;
#pragma unroll
            for (int k = 0; k < KCL; k++) L += sqrtf(g_red[k] + 1e-15f);
            *out_loss = -L / sqrtf((float)Nn * (float)KCL);
        }
    }
}

// ================= launch =================
extern "C" void kernel_launch(void* const* d_in, const int* in_sizes, int n_in,
                              void* d_out, int out_size) {
    const float* x  = (const float*)d_in[0];
    const float* ew = (const float*)d_in[1];
    const float* W1 = (const float*)d_in[2];
    const float* b1 = (const float*)d_in[3];
    const float* W2 = (const float*)d_in[4];
    const float* b2 = (const float*)d_in[5];
    const float* Wm = (const float*)d_in[6];
    const float* bm = (const float*)d_in[7];
    const int*   ei = (const int*)d_in[8];

    int Nn = in_sizes[0] / DIM;
    int E  = in_sizes[1];
    const int* src = ei;
    const int* dst = ei + E;
    float* out = (float*)d_out;

    float* red_buf;
    __half* t_buf;
    __nv_bfloat16 *ab_buf, *wb1_buf, *wb2_buf;
    int* deg_buf;
    cudaGetSymbolAddress((void**)&t_buf, g_t);
    cudaGetSymbolAddress((void**)&ab_buf, g_abig);
    cudaGetSymbolAddress((void**)&wb1_buf, g_wbig1);
    cudaGetSymbolAddress((void**)&wb2_buf, g_wbig2);
    cudaGetSymbolAddress((void**)&deg_buf, g_deg);
    cudaGetSymbolAddress((void**)&red_buf, g_red);

    cudaMemsetAsync(deg_buf, 0, N_NODES * sizeof(int));
    cudaMemsetAsync(red_buf, 0, (KCL + 1) * sizeof(float));

    int FB = E / 512;
    int CA = (Nn * DIM) / 1024;
    k_mega<<<FB + 128 + CA, 256>>>(src, dst, ew, x, W1, W2, FB);

    dim3 gmma(DIM / 64, Nn / 64);
    k_mma<<<gmma, 128>>>(ab_buf, wb1_buf, t_buf);
    k_agg1<<<Nn / 8, 256>>>(t_buf, b1, ab_buf);
    k_mma<<<gmma, 128>>>(ab_buf, wb2_buf, t_buf);
    k_aggmlp<<<Nn / 16, 512>>>(t_buf, b2, Wm, bm, out, out + (out_size - 1), Nn);
}

// round 7
// speedup vs baseline: 1.1983x; 1.1983x over previous
#include <cuda_runtime.h>
#include <cuda_bf16.h>
#include <cuda_fp16.h>
#include <cstdint>
#include <cstring>

#define N_NODES 12288
#define DIM 256
#define KCL 16
#define KW 512               // virtual K: [Wh; Wl]
#define NIT (KW / 32)        // 16
#define CAP 128              // per-node edge bucket capacity

// ---- static device scratch ----
__device__ __half g_t[N_NODES * DIM];                // GEMM output, fp16
__device__ __half g_a[N_NODES * DIM];                // GEMM input (fp16 x, then fp16 h)
__device__ __half g_w1[KW * DIM];                    // [512,256] = [W1h; W1l]
__device__ __half g_w2[KW * DIM];
__device__ int   g_deg[N_NODES];
__device__ int2  g_bucket[N_NODES * CAP];            // (src, bits(w))
__device__ float g_red[KCL + 1];                     // [0:16) colsumsq, [16] ticket

// ================= PTX helpers =================
__device__ __forceinline__ uint32_t smem_u32(const void* p) {
    uint32_t a;
    asm("{ .reg .u64 t; cvta.to.shared.u64 t, %1; cvt.u32.u64 %0, t; }" : "=r"(a) : "l"(p));
    return a;
}
#define CP_ASYNC16(sa, gp) \
    asm volatile("cp.async.cg.shared.global [%0], [%1], 16;" :: "r"(sa), "l"(gp))
#define CP_COMMIT() asm volatile("cp.async.commit_group;" ::: "memory")
#define CP_WAIT(n)  asm volatile("cp.async.wait_group %0;" :: "n"(n) : "memory")

#define LDSM4(r0, r1, r2, r3, a) \
    asm volatile("ldmatrix.sync.aligned.m8n8.x4.shared.b16 {%0,%1,%2,%3}, [%4];" \
                 : "=r"(r0), "=r"(r1), "=r"(r2), "=r"(r3) : "r"(a))
#define LDSM2T(r0, r1, a) \
    asm volatile("ldmatrix.sync.aligned.m8n8.x2.trans.shared.b16 {%0,%1}, [%2];" \
                 : "=r"(r0), "=r"(r1) : "r"(a))
#define MMA16816H(c, a, b) \
    asm volatile("mma.sync.aligned.m16n8k16.row.col.f32.f16.f16.f32 " \
                 "{%0,%1,%2,%3}, {%4,%5,%6,%7}, {%8,%9}, {%0,%1,%2,%3};" \
                 : "+f"((c)[0]), "+f"((c)[1]), "+f"((c)[2]), "+f"((c)[3]) \
                 : "r"((a)[0]), "r"((a)[1]), "r"((a)[2]), "r"((a)[3]), \
                   "r"((b)[0]), "r"((b)[1]))

__device__ __forceinline__ uint32_t h2_pack(float a, float b) {
    __half2 t = __floats2half2_rn(a, b);
    uint32_t u;
    memcpy(&u, &t, 4);
    return u;
}

// ================= mega prologue: bucket-fill + convW1 + convW2 + convA =================
// blocks: [0,FB) fill | [FB,FB+64) W1 | [FB+64,FB+128) W2 | rest: x->fp16 (8 elems/thr)
__global__ __launch_bounds__(256) void k_mega(const int* __restrict__ src,
                                              const int* __restrict__ dst,
                                              const float* __restrict__ ew,
                                              const float* __restrict__ x,
                                              const float* __restrict__ W1,
                                              const float* __restrict__ W2,
                                              int FB) {
    int b = blockIdx.x, tid = threadIdx.x;
    if (b < FB) {
        int e = (b * 256 + tid) * 2;
        int2 s2 = *(const int2*)(src + e);
        int2 d2 = *(const int2*)(dst + e);
        float2 w2 = *(const float2*)(ew + e);
        int p = atomicAdd(&g_deg[d2.x], 1);
        if (p < CAP) g_bucket[(size_t)d2.x * CAP + p] = make_int2(s2.x, __float_as_int(w2.x));
        p = atomicAdd(&g_deg[d2.y], 1);
        if (p < CAP) g_bucket[(size_t)d2.y * CAP + p] = make_int2(s2.y, __float_as_int(w2.y));
    } else if (b < FB + 128) {
        int rel = b - FB;
        const float* W = (rel < 64) ? W1 : W2;
        __half* Wt = (rel < 64) ? g_w1 : g_w2;
        int idx = ((rel & 63) * 256 + tid) * 4;
        float4 v = *(const float4*)(W + idx);
        int k = idx >> 8, n = idx & 255;
        float hx = __half2float(__float2half_rn(v.x));
        float hy = __half2float(__float2half_rn(v.y));
        float hz = __half2float(__float2half_rn(v.z));
        float hw = __half2float(__float2half_rn(v.w));
        *(uint2*)&Wt[(size_t)k * DIM + n] =
            make_uint2(h2_pack(v.x, v.y), h2_pack(v.z, v.w));
        *(uint2*)&Wt[(size_t)(k + 256) * DIM + n] =
            make_uint2(h2_pack(v.x - hx, v.y - hy), h2_pack(v.z - hz, v.w - hw));
    } else {
        int idx = ((b - FB - 128) * 256 + tid) * 8;
        float4 v0 = *(const float4*)(x + idx);
        float4 v1 = *(const float4*)(x + idx + 4);
        *(uint4*)&g_a[idx] = make_uint4(h2_pack(v0.x, v0.y), h2_pack(v0.z, v0.w),
                                        h2_pack(v1.x, v1.y), h2_pack(v1.z, v1.w));
    }
}

// ================= mma.sync fp16 GEMM: t[12288,256] = A @ (Wh + Wl) =================
// BM=64, BN=128, BK=32, 256 thr (8 warps 2x4), warp tile 32x32, 3-stage ring
#define APITCH 40
#define BPITCH 136
#define A_ST (64 * APITCH)
#define B_ST (32 * BPITCH)

__global__ __launch_bounds__(256, 3) void k_mma(const __half* __restrict__ Ah,
                                                const __half* __restrict__ Wh,
                                                __half* __restrict__ C) {
    __shared__ __align__(16) __half As[3 * A_ST];
    __shared__ __align__(16) __half Bs[3 * B_ST];
    int tid = threadIdx.x;
    int bm = blockIdx.y * 64, bn = blockIdx.x * 128;
    int warp = tid >> 5, lane = tid & 31;
    int wr = warp >> 2, wc = warp & 3;

    float acc[2][4][4];
#pragma unroll
    for (int i = 0; i < 2; i++)
#pragma unroll
        for (int j = 0; j < 4; j++)
#pragma unroll
            for (int f = 0; f < 4; f++) acc[i][j][f] = 0.f;

    // load mapping: A row=tid>>2 (0-63), col=(tid&3)*8; B rows tid>>4 and +16, col=(tid&15)*8
    int ar = tid >> 2, ac = (tid & 3) * 8;
    int br = tid >> 4, bc = (tid & 15) * 8;

    uint32_t sA0 = smem_u32(&As[ar * APITCH + ac]);
    uint32_t sB0 = smem_u32(&Bs[br * BPITCH + bc]);
    uint32_t sB1 = smem_u32(&Bs[(br + 16) * BPITCH + bc]);
    uint32_t lA0 = smem_u32(&As[(wr * 32 + (lane & 15)) * APITCH + ((lane >> 4) << 3)]);
    uint32_t lB0 = smem_u32(&Bs[(lane & 15) * BPITCH + wc * 32]);

    const __half* gA = Ah + (size_t)(bm + ar) * DIM + ac;   // + (k0 & 255)
    const __half* gB = Wh + (size_t)br * DIM + bn + bc;     // + k0 * DIM

#define LOAD_TILE(i, slot)                                                   \
    do {                                                                     \
        int k0 = (i) * 32;                                                   \
        const __half* ga = gA + (k0 & 255);                                  \
        const __half* gb = gB + (size_t)k0 * DIM;                            \
        CP_ASYNC16(sA0 + (slot) * (A_ST * 2), ga);                           \
        CP_ASYNC16(sB0 + (slot) * (B_ST * 2), gb);                           \
        CP_ASYNC16(sB1 + (slot) * (B_ST * 2), gb + 16 * DIM);                \
    } while (0)

    LOAD_TILE(0, 0); CP_COMMIT();
    LOAD_TILE(1, 1); CP_COMMIT();

    int slot = 0, nslot = 2;
    for (int i = 0; i < NIT; i++) {
        CP_WAIT(1);
        __syncthreads();
        if (i + 2 < NIT) LOAD_TILE(i + 2, nslot);
        CP_COMMIT();
        uint32_t lA = lA0 + slot * (A_ST * 2);
        uint32_t lB = lB0 + slot * (B_ST * 2);
#pragma unroll
        for (int kt = 0; kt < 2; kt++) {
            uint32_t a[2][4];
#pragma unroll
            for (int mt = 0; mt < 2; mt++)
                LDSM4(a[mt][0], a[mt][1], a[mt][2], a[mt][3],
                      lA + (mt * 16 * APITCH + kt * 16) * 2);
            uint32_t b[4][2];
#pragma unroll
            for (int nt = 0; nt < 4; nt++)
                LDSM2T(b[nt][0], b[nt][1], lB + (kt * 16 * BPITCH + nt * 8) * 2);
#pragma unroll
            for (int mt = 0; mt < 2; mt++)
#pragma unroll
                for (int nt = 0; nt < 4; nt++) MMA16816H(acc[mt][nt], a[mt], b[nt]);
        }
        slot++; if (slot >= 3) slot = 0;
        nslot++; if (nslot >= 3) nslot = 0;
    }

#pragma unroll
    for (int mt = 0; mt < 2; mt++)
#pragma unroll
        for (int nt = 0; nt < 4; nt++) {
            int row = bm + wr * 32 + mt * 16 + (lane >> 2);
            int col = bn + wc * 32 + nt * 8 + (lane & 3) * 2;
            *(__half2*)&C[(size_t)row * DIM + col] =
                __floats2half2_rn(acc[mt][nt][0], acc[mt][nt][1]);
            *(__half2*)&C[(size_t)(row + 8) * DIM + col] =
                __floats2half2_rn(acc[mt][nt][2], acc[mt][nt][3]);
        }
}

// ================= gather core: warp-per-node, lane owns cols [8l, 8l+8), fp16 t =================
__device__ __forceinline__ void gather_node(const __half* __restrict__ t,
                                            const float* __restrict__ bias,
                                            int node, int lane,
                                            float4& a0, float4& a1) {
    a0 = *(const float4*)&bias[8 * lane];
    a1 = *(const float4*)&bias[8 * lane + 4];
    int cnt = min(g_deg[node], CAP);
    const int2* bk = g_bucket + (size_t)node * CAP;
    for (int j0 = 0; j0 < cnt; j0 += 32) {
        int2 e = make_int2(0, 0);
        if (j0 + lane < cnt) e = bk[j0 + lane];
        int m = min(32, cnt - j0);
#pragma unroll 4
        for (int j = 0; j < m; j++) {
            int s = __shfl_sync(0xffffffffu, e.x, j);
            float w = __int_as_float(__shfl_sync(0xffffffffu, e.y, j));
            uint4 v = *(const uint4*)(t + (size_t)s * DIM + 8 * lane);
            float2 f0 = __half22float2(*(__half2*)&v.x);
            float2 f1 = __half22float2(*(__half2*)&v.y);
            float2 f2 = __half22float2(*(__half2*)&v.z);
            float2 f3 = __half22float2(*(__half2*)&v.w);
            a0.x += w * f0.x; a0.y += w * f0.y; a0.z += w * f1.x; a0.w += w * f1.y;
            a1.x += w * f2.x; a1.y += w * f2.y; a1.z += w * f3.x; a1.w += w * f3.y;
        }
    }
    a0.x = fmaxf(a0.x, 0.f); a0.y = fmaxf(a0.y, 0.f);
    a0.z = fmaxf(a0.z, 0.f); a0.w = fmaxf(a0.w, 0.f);
    a1.x = fmaxf(a1.x, 0.f); a1.y = fmaxf(a1.y, 0.f);
    a1.z = fmaxf(a1.z, 0.f); a1.w = fmaxf(a1.w, 0.f);
}

// ================= agg layer 1: gather + relu -> fp16 =================
__global__ __launch_bounds__(256) void k_agg1(const __half* __restrict__ t,
                                              const float* __restrict__ bias,
                                              __half* __restrict__ outh) {
    int warp = threadIdx.x >> 5, lane = threadIdx.x & 31;
    int node = blockIdx.x * 8 + warp;
    float4 a0, a1;
    gather_node(t, bias, node, lane, a0, a1);
    *(uint4*)&outh[(size_t)node * DIM + 8 * lane] =
        make_uint4(h2_pack(a0.x, a0.y), h2_pack(a0.z, a0.w),
                   h2_pack(a1.x, a1.y), h2_pack(a1.z, a1.w));
}

// ================= fused agg2 + MLP + softmax + colsumsq + loss (ticket) =================
__global__ __launch_bounds__(512) void k_aggmlp(const __half* __restrict__ t,
                                                const float* __restrict__ bias,
                                                const float* __restrict__ Wm,
                                                const float* __restrict__ bm,
                                                float* __restrict__ out,
                                                float* __restrict__ out_loss, int Nn) {
    __shared__ float sW[KCL * DIM];
    __shared__ float sh[16][DIM];
    __shared__ float part[16][KCL];
    __shared__ float sbm[KCL];
    int tid = threadIdx.x;
    for (int idx = tid; idx < KCL * DIM; idx += 512)
        sW[idx] = Wm[(idx & 255) * KCL + (idx >> 8)];
    if (tid < KCL) sbm[tid] = bm[tid];

    int warp = tid >> 5, lane = tid & 31;
    int node = blockIdx.x * 16 + warp;
    float4 a0, a1;
    gather_node(t, bias, node, lane, a0, a1);
    *(float4*)&sh[warp][8 * lane] = a0;
    *(float4*)&sh[warp][8 * lane + 4] = a1;
    __syncthreads();

    float acc[KCL];
#pragma unroll
    for (int k = 0; k < KCL; k++) acc[k] = 0.f;
#pragma unroll
    for (int m = 0; m < 8; m++) {
        float hv = sh[warp][lane + 32 * m];
#pragma unroll
        for (int k = 0; k < KCL; k++) acc[k] += hv * sW[k * DIM + lane + 32 * m];
    }
#pragma unroll
    for (int off = 16; off >= 1; off >>= 1)
#pragma unroll
        for (int k = 0; k < KCL; k++) acc[k] += __shfl_xor_sync(0xffffffffu, acc[k], off);

    if (lane < KCL) {
        float logit = acc[lane] + sbm[lane];
        float mx = logit;
#pragma unroll
        for (int off = 8; off >= 1; off >>= 1) mx = fmaxf(mx, __shfl_xor_sync(0xffffu, mx, off));
        float e = expf(logit - mx);
        float se = e;
#pragma unroll
        for (int off = 8; off >= 1; off >>= 1) se += __shfl_xor_sync(0xffffu, se, off);
        float sv = e / se;
        out[(size_t)node * KCL + lane] = sv;
        part[warp][lane] = sv * sv;
    }
    __syncthreads();
    if (tid < KCL) {
        float s = 0.f;
#pragma unroll
        for (int w = 0; w < 16; w++) s += part[w][tid];
        atomicAdd(&g_red[tid], s);
    }
    __syncthreads();
    if (tid == 0) {
        __threadfence();
        int prev = atomicAdd((int*)&g_red[KCL], 1);
        if (prev == (int)gridDim.x - 1) {
            float L = 0.f;
#pragma unroll
            for (int k = 0; k < KCL; k++) L += sqrtf(g_red[k] + 1e-15f);
            *out_loss = -L / sqrtf((float)Nn * (float)KCL);
        }
    }
}

// ================= launch =================
extern "C" void kernel_launch(void* const* d_in, const int* in_sizes, int n_in,
                              void* d_out, int out_size) {
    const float* x  = (const float*)d_in[0];
    const float* ew = (const float*)d_in[1];
    const float* W1 = (const float*)d_in[2];
    const float* b1 = (const float*)d_in[3];
    const float* W2 = (const float*)d_in[4];
    const float* b2 = (const float*)d_in[5];
    const float* Wm = (const float*)d_in[6];
    const float* bm = (const float*)d_in[7];
    const int*   ei = (const int*)d_in[8];

    int Nn = in_sizes[0] / DIM;
    int E  = in_sizes[1];
    const int* src = ei;
    const int* dst = ei + E;
    float* out = (float*)d_out;

    float* red_buf;
    __half *t_buf, *a_buf, *w1_buf, *w2_buf;
    int* deg_buf;
    cudaGetSymbolAddress((void**)&t_buf, g_t);
    cudaGetSymbolAddress((void**)&a_buf, g_a);
    cudaGetSymbolAddress((void**)&w1_buf, g_w1);
    cudaGetSymbolAddress((void**)&w2_buf, g_w2);
    cudaGetSymbolAddress((void**)&deg_buf, g_deg);
    cudaGetSymbolAddress((void**)&red_buf, g_red);

    cudaMemsetAsync(deg_buf, 0, N_NODES * sizeof(int));
    cudaMemsetAsync(red_buf, 0, (KCL + 1) * sizeof(float));

    int FB = E / 512;
    int CA = (Nn * DIM) / 2048;
    k_mega<<<FB + 128 + CA, 256>>>(src, dst, ew, x, W1, W2, FB);

    dim3 gmma(DIM / 128, Nn / 64);
    k_mma<<<gmma, 256>>>(a_buf, w1_buf, t_buf);
    k_agg1<<<Nn / 8, 256>>>(t_buf, b1, a_buf);
    k_mma<<<gmma, 256>>>(a_buf, w2_buf, t_buf);
    k_aggmlp<<<Nn / 16, 512>>>(t_buf, b2, Wm, bm, out, out + (out_size - 1), Nn);
}

// round 8
// speedup vs baseline: 1.1986x; 1.0003x over previous
#include <cuda_runtime.h>
#include <cuda_bf16.h>
#include <cuda_fp16.h>
#include <cstdint>
#include <cstring>

#define N_NODES 12288
#define DIM 256
#define KCL 16
#define KW 512               // virtual K: [Wh; Wl]
#define NIT (KW / 32)        // 16
#define CAP 128              // per-node edge bucket capacity
#define STAGES 5

// ---- static device scratch ----
__device__ __half g_t[N_NODES * DIM];                // GEMM output, fp16
__device__ __half g_a[N_NODES * DIM];                // GEMM input (fp16 x, then fp16 h)
__device__ __half g_w1[KW * DIM];                    // [512,256] = [W1h; W1l]
__device__ __half g_w2[KW * DIM];
__device__ int   g_deg[N_NODES];
__device__ int2  g_bucket[N_NODES * CAP];            // (src, bits(w))
__device__ float g_red[KCL + 1];                     // [0:16) colsumsq, [16] ticket

// ================= PTX helpers =================
__device__ __forceinline__ uint32_t smem_u32(const void* p) {
    uint32_t a;
    asm("{ .reg .u64 t; cvta.to.shared.u64 t, %1; cvt.u32.u64 %0, t; }" : "=r"(a) : "l"(p));
    return a;
}
#define CP_ASYNC16(sa, gp) \
    asm volatile("cp.async.cg.shared.global [%0], [%1], 16;" :: "r"(sa), "l"(gp))
#define CP_COMMIT() asm volatile("cp.async.commit_group;" ::: "memory")
#define CP_WAIT(n)  asm volatile("cp.async.wait_group %0;" :: "n"(n) : "memory")

#define LDSM4(r0, r1, r2, r3, a) \
    asm volatile("ldmatrix.sync.aligned.m8n8.x4.shared.b16 {%0,%1,%2,%3}, [%4];" \
                 : "=r"(r0), "=r"(r1), "=r"(r2), "=r"(r3) : "r"(a))
#define LDSM2T(r0, r1, a) \
    asm volatile("ldmatrix.sync.aligned.m8n8.x2.trans.shared.b16 {%0,%1}, [%2];" \
                 : "=r"(r0), "=r"(r1) : "r"(a))
#define MMA16816H(c, a, b) \
    asm volatile("mma.sync.aligned.m16n8k16.row.col.f32.f16.f16.f32 " \
                 "{%0,%1,%2,%3}, {%4,%5,%6,%7}, {%8,%9}, {%0,%1,%2,%3};" \
                 : "+f"((c)[0]), "+f"((c)[1]), "+f"((c)[2]), "+f"((c)[3]) \
                 : "r"((a)[0]), "r"((a)[1]), "r"((a)[2]), "r"((a)[3]), \
                   "r"((b)[0]), "r"((b)[1]))

__device__ __forceinline__ uint32_t h2_pack(float a, float b) {
    __half2 t = __floats2half2_rn(a, b);
    uint32_t u;
    memcpy(&u, &t, 4);
    return u;
}

// ================= mega prologue: bucket-fill + convW1 + convW2 + convA =================
__global__ __launch_bounds__(256) void k_mega(const int* __restrict__ src,
                                              const int* __restrict__ dst,
                                              const float* __restrict__ ew,
                                              const float* __restrict__ x,
                                              const float* __restrict__ W1,
                                              const float* __restrict__ W2,
                                              int FB) {
    int b = blockIdx.x, tid = threadIdx.x;
    if (b < FB) {
        int e = (b * 256 + tid) * 2;
        int2 s2 = *(const int2*)(src + e);
        int2 d2 = *(const int2*)(dst + e);
        float2 w2 = *(const float2*)(ew + e);
        int p = atomicAdd(&g_deg[d2.x], 1);
        if (p < CAP) g_bucket[(size_t)d2.x * CAP + p] = make_int2(s2.x, __float_as_int(w2.x));
        p = atomicAdd(&g_deg[d2.y], 1);
        if (p < CAP) g_bucket[(size_t)d2.y * CAP + p] = make_int2(s2.y, __float_as_int(w2.y));
    } else if (b < FB + 128) {
        int rel = b - FB;
        const float* W = (rel < 64) ? W1 : W2;
        __half* Wt = (rel < 64) ? g_w1 : g_w2;
        int idx = ((rel & 63) * 256 + tid) * 4;
        float4 v = *(const float4*)(W + idx);
        int k = idx >> 8, n = idx & 255;
        float hx = __half2float(__float2half_rn(v.x));
        float hy = __half2float(__float2half_rn(v.y));
        float hz = __half2float(__float2half_rn(v.z));
        float hw = __half2float(__float2half_rn(v.w));
        *(uint2*)&Wt[(size_t)k * DIM + n] =
            make_uint2(h2_pack(v.x, v.y), h2_pack(v.z, v.w));
        *(uint2*)&Wt[(size_t)(k + 256) * DIM + n] =
            make_uint2(h2_pack(v.x - hx, v.y - hy), h2_pack(v.z - hz, v.w - hw));
    } else {
        int idx = ((b - FB - 128) * 256 + tid) * 8;
        float4 v0 = *(const float4*)(x + idx);
        float4 v1 = *(const float4*)(x + idx + 4);
        *(uint4*)&g_a[idx] = make_uint4(h2_pack(v0.x, v0.y), h2_pack(v0.z, v0.w),
                                        h2_pack(v1.x, v1.y), h2_pack(v1.z, v1.w));
    }
}

// ================= mma.sync fp16 GEMM: t[12288,256] = A @ (Wh + Wl) =================
// BM=64, BN=128, BK=32, 256 thr (8 warps 2x4), warp tile 32x32, 5-stage ring (dynamic smem)
#define APITCH 40
#define BPITCH 136
#define A_ST (64 * APITCH)
#define B_ST (32 * BPITCH)
#define SMEM_MMA (STAGES * (A_ST + B_ST) * 2)

__global__ __launch_bounds__(256, 3) void k_mma(const __half* __restrict__ Ah,
                                                const __half* __restrict__ Wh,
                                                __half* __restrict__ C) {
    extern __shared__ __align__(16) __half dsm[];
    __half* As = dsm;                       // STAGES * A_ST
    __half* Bs = dsm + STAGES * A_ST;       // STAGES * B_ST
    int tid = threadIdx.x;
    int bm = blockIdx.y * 64, bn = blockIdx.x * 128;
    int warp = tid >> 5, lane = tid & 31;
    int wr = warp >> 2, wc = warp & 3;

    float acc[2][4][4];
#pragma unroll
    for (int i = 0; i < 2; i++)
#pragma unroll
        for (int j = 0; j < 4; j++)
#pragma unroll
            for (int f = 0; f < 4; f++) acc[i][j][f] = 0.f;

    int ar = tid >> 2, ac = (tid & 3) * 8;
    int br = tid >> 4, bc = (tid & 15) * 8;

    uint32_t sA0 = smem_u32(&As[ar * APITCH + ac]);
    uint32_t sB0 = smem_u32(&Bs[br * BPITCH + bc]);
    uint32_t sB1 = smem_u32(&Bs[(br + 16) * BPITCH + bc]);
    uint32_t lA0 = smem_u32(&As[(wr * 32 + (lane & 15)) * APITCH + ((lane >> 4) << 3)]);
    uint32_t lB0 = smem_u32(&Bs[(lane & 15) * BPITCH + wc * 32]);

    const __half* gA = Ah + (size_t)(bm + ar) * DIM + ac;   // + (k0 & 255)
    const __half* gB = Wh + (size_t)br * DIM + bn + bc;     // + k0 * DIM

#define LOAD_TILE(i, slot)                                                   \
    do {                                                                     \
        int k0 = (i) * 32;                                                   \
        const __half* ga = gA + (k0 & 255);                                  \
        const __half* gb = gB + (size_t)k0 * DIM;                            \
        CP_ASYNC16(sA0 + (slot) * (A_ST * 2), ga);                           \
        CP_ASYNC16(sB0 + (slot) * (B_ST * 2), gb);                           \
        CP_ASYNC16(sB1 + (slot) * (B_ST * 2), gb + 16 * DIM);                \
    } while (0)

    LOAD_TILE(0, 0); CP_COMMIT();
    LOAD_TILE(1, 1); CP_COMMIT();
    LOAD_TILE(2, 2); CP_COMMIT();
    LOAD_TILE(3, 3); CP_COMMIT();

    int slot = 0, pslot = 4;
    for (int i = 0; i < NIT; i++) {
        CP_WAIT(3);
        __syncthreads();
        if (i + 4 < NIT) LOAD_TILE(i + 4, pslot);
        CP_COMMIT();
        uint32_t lA = lA0 + slot * (A_ST * 2);
        uint32_t lB = lB0 + slot * (B_ST * 2);
#pragma unroll
        for (int kt = 0; kt < 2; kt++) {
            uint32_t a[2][4];
#pragma unroll
            for (int mt = 0; mt < 2; mt++)
                LDSM4(a[mt][0], a[mt][1], a[mt][2], a[mt][3],
                      lA + (mt * 16 * APITCH + kt * 16) * 2);
            uint32_t b[4][2];
#pragma unroll
            for (int nt = 0; nt < 4; nt++)
                LDSM2T(b[nt][0], b[nt][1], lB + (kt * 16 * BPITCH + nt * 8) * 2);
#pragma unroll
            for (int mt = 0; mt < 2; mt++)
#pragma unroll
                for (int nt = 0; nt < 4; nt++) MMA16816H(acc[mt][nt], a[mt], b[nt]);
        }
        if (++slot == STAGES) slot = 0;
        if (++pslot == STAGES) pslot = 0;
    }

#pragma unroll
    for (int mt = 0; mt < 2; mt++)
#pragma unroll
        for (int nt = 0; nt < 4; nt++) {
            int row = bm + wr * 32 + mt * 16 + (lane >> 2);
            int col = bn + wc * 32 + nt * 8 + (lane & 3) * 2;
            *(__half2*)&C[(size_t)row * DIM + col] =
                __floats2half2_rn(acc[mt][nt][0], acc[mt][nt][1]);
            *(__half2*)&C[(size_t)(row + 8) * DIM + col] =
                __floats2half2_rn(acc[mt][nt][2], acc[mt][nt][3]);
        }
}

// ================= gather core: warp-per-node, lane owns cols [8l, 8l+8), fp16 t =================
__device__ __forceinline__ void gather_node(const __half* __restrict__ t,
                                            const float* __restrict__ bias,
                                            int node, int lane,
                                            float4& a0, float4& a1) {
    a0 = *(const float4*)&bias[8 * lane];
    a1 = *(const float4*)&bias[8 * lane + 4];
    int cnt = min(g_deg[node], CAP);
    const int2* bk = g_bucket + (size_t)node * CAP;
    for (int j0 = 0; j0 < cnt; j0 += 32) {
        int2 e = make_int2(0, 0);
        if (j0 + lane < cnt) e = bk[j0 + lane];
        int m = min(32, cnt - j0);
#pragma unroll 4
        for (int j = 0; j < m; j++) {
            int s = __shfl_sync(0xffffffffu, e.x, j);
            float w = __int_as_float(__shfl_sync(0xffffffffu, e.y, j));
            uint4 v = *(const uint4*)(t + (size_t)s * DIM + 8 * lane);
            float2 f0 = __half22float2(*(__half2*)&v.x);
            float2 f1 = __half22float2(*(__half2*)&v.y);
            float2 f2 = __half22float2(*(__half2*)&v.z);
            float2 f3 = __half22float2(*(__half2*)&v.w);
            a0.x += w * f0.x; a0.y += w * f0.y; a0.z += w * f1.x; a0.w += w * f1.y;
            a1.x += w * f2.x; a1.y += w * f2.y; a1.z += w * f3.x; a1.w += w * f3.y;
        }
    }
    a0.x = fmaxf(a0.x, 0.f); a0.y = fmaxf(a0.y, 0.f);
    a0.z = fmaxf(a0.z, 0.f); a0.w = fmaxf(a0.w, 0.f);
    a1.x = fmaxf(a1.x, 0.f); a1.y = fmaxf(a1.y, 0.f);
    a1.z = fmaxf(a1.z, 0.f); a1.w = fmaxf(a1.w, 0.f);
}

// ================= agg layer 1: gather + relu -> fp16 =================
__global__ __launch_bounds__(256) void k_agg1(const __half* __restrict__ t,
                                              const float* __restrict__ bias,
                                              __half* __restrict__ outh) {
    int warp = threadIdx.x >> 5, lane = threadIdx.x & 31;
    int node = blockIdx.x * 8 + warp;
    float4 a0, a1;
    gather_node(t, bias, node, lane, a0, a1);
    *(uint4*)&outh[(size_t)node * DIM + 8 * lane] =
        make_uint4(h2_pack(a0.x, a0.y), h2_pack(a0.z, a0.w),
                   h2_pack(a1.x, a1.y), h2_pack(a1.z, a1.w));
}

// ================= fused agg2 + MLP + softmax + colsumsq + loss (ticket) =================
__global__ __launch_bounds__(512) void k_aggmlp(const __half* __restrict__ t,
                                                const float* __restrict__ bias,
                                                const float* __restrict__ Wm,
                                                const float* __restrict__ bm,
                                                float* __restrict__ out,
                                                float* __restrict__ out_loss, int Nn) {
    __shared__ float sW[KCL * DIM];
    __shared__ float sh[16][DIM];
    __shared__ float part[16][KCL];
    __shared__ float sbm[KCL];
    int tid = threadIdx.x;
    for (int idx = tid; idx < KCL * DIM; idx += 512)
        sW[idx] = Wm[(idx & 255) * KCL + (idx >> 8)];
    if (tid < KCL) sbm[tid] = bm[tid];

    int warp = tid >> 5, lane = tid & 31;
    int node = blockIdx.x * 16 + warp;
    float4 a0, a1;
    gather_node(t, bias, node, lane, a0, a1);
    *(float4*)&sh[warp][8 * lane] = a0;
    *(float4*)&sh[warp][8 * lane + 4] = a1;
    __syncthreads();

    float acc[KCL];
#pragma unroll
    for (int k = 0; k < KCL; k++) acc[k] = 0.f;
#pragma unroll
    for (int m = 0; m < 8; m++) {
        float hv = sh[warp][lane + 32 * m];
#pragma unroll
        for (int k = 0; k < KCL; k++) acc[k] += hv * sW[k * DIM + lane + 32 * m];
    }
#pragma unroll
    for (int off = 16; off >= 1; off >>= 1)
#pragma unroll
        for (int k = 0; k < KCL; k++) acc[k] += __shfl_xor_sync(0xffffffffu, acc[k], off);

    if (lane < KCL) {
        float logit = acc[lane] + sbm[lane];
        float mx = logit;
#pragma unroll
        for (int off = 8; off >= 1; off >>= 1) mx = fmaxf(mx, __shfl_xor_sync(0xffffu, mx, off));
        float e = expf(logit - mx);
        float se = e;
#pragma unroll
        for (int off = 8; off >= 1; off >>= 1) se += __shfl_xor_sync(0xffffu, se, off);
        float sv = e / se;
        out[(size_t)node * KCL + lane] = sv;
        part[warp][lane] = sv * sv;
    }
    __syncthreads();
    if (tid < KCL) {
        float s = 0.f;
#pragma unroll
        for (int w = 0; w < 16; w++) s += part[w][tid];
        atomicAdd(&g_red[tid], s);
    }
    __syncthreads();
    if (tid == 0) {
        __threadfence();
        int prev = atomicAdd((int*)&g_red[KCL], 1);
        if (prev == (int)gridDim.x - 1) {
            float L = 0.f;
#pragma unroll
            for (int k = 0; k < KCL; k++) L += sqrtf(g_red[k] + 1e-15f);
            *out_loss = -L / sqrtf((float)Nn * (float)KCL);
        }
    }
}

// ================= launch =================
extern "C" void kernel_launch(void* const* d_in, const int* in_sizes, int n_in,
                              void* d_out, int out_size) {
    const float* x  = (const float*)d_in[0];
    const float* ew = (const float*)d_in[1];
    const float* W1 = (const float*)d_in[2];
    const float* b1 = (const float*)d_in[3];
    const float* W2 = (const float*)d_in[4];
    const float* b2 = (const float*)d_in[5];
    const float* Wm = (const float*)d_in[6];
    const float* bm = (const float*)d_in[7];
    const int*   ei = (const int*)d_in[8];

    int Nn = in_sizes[0] / DIM;
    int E  = in_sizes[1];
    const int* src = ei;
    const int* dst = ei + E;
    float* out = (float*)d_out;

    float* red_buf;
    __half *t_buf, *a_buf, *w1_buf, *w2_buf;
    int* deg_buf;
    cudaGetSymbolAddress((void**)&t_buf, g_t);
    cudaGetSymbolAddress((void**)&a_buf, g_a);
    cudaGetSymbolAddress((void**)&w1_buf, g_w1);
    cudaGetSymbolAddress((void**)&w2_buf, g_w2);
    cudaGetSymbolAddress((void**)&deg_buf, g_deg);
    cudaGetSymbolAddress((void**)&red_buf, g_red);

    cudaFuncSetAttribute(k_mma, cudaFuncAttributeMaxDynamicSharedMemorySize, SMEM_MMA);

    cudaMemsetAsync(deg_buf, 0, N_NODES * sizeof(int));
    cudaMemsetAsync(red_buf, 0, (KCL + 1) * sizeof(float));

    int FB = E / 512;
    int CA = (Nn * DIM) / 2048;
    k_mega<<<FB + 128 + CA, 256>>>(src, dst, ew, x, W1, W2, FB);

    dim3 gmma(DIM / 128, Nn / 64);
    k_mma<<<gmma, 256, SMEM_MMA>>>(a_buf, w1_buf, t_buf);
    k_agg1<<<Nn / 8, 256>>>(t_buf, b1, a_buf);
    k_mma<<<gmma, 256, SMEM_MMA>>>(a_buf, w2_buf, t_buf);
    k_aggmlp<<<Nn / 16, 512>>>(t_buf, b2, Wm, bm, out, out + (out_size - 1), Nn);
}

// round 9
// speedup vs baseline: 1.3287x; 1.1085x over previous
#include <cuda_runtime.h>
#include <cuda_bf16.h>
#include <cuda_fp16.h>
#include <cstdint>
#include <cstring>

#define N_NODES 12288
#define DIM 256
#define KCL 16
#define KW 256               // plain fp16 W, K = 256
#define NIT (KW / 32)        // 8
#define CAP 128              // per-node edge bucket capacity
#define STAGES 4

// ---- static device scratch ----
__device__ __half g_t[N_NODES * DIM];                // GEMM output, fp16
__device__ __half g_a[N_NODES * DIM];                // GEMM input (fp16 x, then fp16 h)
__device__ __half g_w1[KW * DIM];                    // [256,256] fp16
__device__ __half g_w2[KW * DIM];
__device__ int   g_deg[N_NODES];
__device__ int2  g_bucket[N_NODES * CAP];            // (src, bits(w))
__device__ float g_red[KCL + 1];                     // [0:16) colsumsq, [16] ticket

// ================= PTX helpers =================
__device__ __forceinline__ uint32_t smem_u32(const void* p) {
    uint32_t a;
    asm("{ .reg .u64 t; cvta.to.shared.u64 t, %1; cvt.u32.u64 %0, t; }" : "=r"(a) : "l"(p));
    return a;
}
#define CP_ASYNC16(sa, gp) \
    asm volatile("cp.async.cg.shared.global [%0], [%1], 16;" :: "r"(sa), "l"(gp))
#define CP_COMMIT() asm volatile("cp.async.commit_group;" ::: "memory")
#define CP_WAIT(n)  asm volatile("cp.async.wait_group %0;" :: "n"(n) : "memory")

#define LDSM4(r0, r1, r2, r3, a) \
    asm volatile("ldmatrix.sync.aligned.m8n8.x4.shared.b16 {%0,%1,%2,%3}, [%4];" \
                 : "=r"(r0), "=r"(r1), "=r"(r2), "=r"(r3) : "r"(a))
#define LDSM2T(r0, r1, a) \
    asm volatile("ldmatrix.sync.aligned.m8n8.x2.trans.shared.b16 {%0,%1}, [%2];" \
                 : "=r"(r0), "=r"(r1) : "r"(a))
#define MMA16816H(c, a, b) \
    asm volatile("mma.sync.aligned.m16n8k16.row.col.f32.f16.f16.f32 " \
                 "{%0,%1,%2,%3}, {%4,%5,%6,%7}, {%8,%9}, {%0,%1,%2,%3};" \
                 : "+f"((c)[0]), "+f"((c)[1]), "+f"((c)[2]), "+f"((c)[3]) \
                 : "r"((a)[0]), "r"((a)[1]), "r"((a)[2]), "r"((a)[3]), \
                   "r"((b)[0]), "r"((b)[1]))

__device__ __forceinline__ uint32_t h2_pack(float a, float b) {
    __half2 t = __floats2half2_rn(a, b);
    uint32_t u;
    memcpy(&u, &t, 4);
    return u;
}

// ================= mega prologue: bucket-fill + convW1 + convW2 + convA =================
// blocks: [0,FB) fill | [FB,FB+32) W1 | [FB+32,FB+64) W2 | rest: x->fp16 (8 elems/thr)
__global__ __launch_bounds__(256) void k_mega(const int* __restrict__ src,
                                              const int* __restrict__ dst,
                                              const float* __restrict__ ew,
                                              const float* __restrict__ x,
                                              const float* __restrict__ W1,
                                              const float* __restrict__ W2,
                                              int FB) {
    int b = blockIdx.x, tid = threadIdx.x;
    if (b < FB) {
        int e = (b * 256 + tid) * 2;
        int2 s2 = *(const int2*)(src + e);
        int2 d2 = *(const int2*)(dst + e);
        float2 w2 = *(const float2*)(ew + e);
        int p = atomicAdd(&g_deg[d2.x], 1);
        if (p < CAP) g_bucket[(size_t)d2.x * CAP + p] = make_int2(s2.x, __float_as_int(w2.x));
        p = atomicAdd(&g_deg[d2.y], 1);
        if (p < CAP) g_bucket[(size_t)d2.y * CAP + p] = make_int2(s2.y, __float_as_int(w2.y));
    } else if (b < FB + 64) {
        int rel = b - FB;
        const float* W = (rel < 32) ? W1 : W2;
        __half* Wt = (rel < 32) ? g_w1 : g_w2;
        int idx = ((rel & 31) * 256 + tid) * 8;
        float4 v0 = *(const float4*)(W + idx);
        float4 v1 = *(const float4*)(W + idx + 4);
        *(uint4*)&Wt[idx] = make_uint4(h2_pack(v0.x, v0.y), h2_pack(v0.z, v0.w),
                                       h2_pack(v1.x, v1.y), h2_pack(v1.z, v1.w));
    } else {
        int idx = ((b - FB - 64) * 256 + tid) * 8;
        float4 v0 = *(const float4*)(x + idx);
        float4 v1 = *(const float4*)(x + idx + 4);
        *(uint4*)&g_a[idx] = make_uint4(h2_pack(v0.x, v0.y), h2_pack(v0.z, v0.w),
                                        h2_pack(v1.x, v1.y), h2_pack(v1.z, v1.w));
    }
}

// ================= mma.sync fp16 GEMM: t[12288,256] = A @ W =================
// BM=64, BN=128, BK=32, 256 thr (8 warps 2x4), warp tile 32x32, 4-stage ring (dynamic smem)
#define APITCH 40
#define BPITCH 136
#define A_ST (64 * APITCH)
#define B_ST (32 * BPITCH)
#define SMEM_MMA (STAGES * (A_ST + B_ST) * 2)

__global__ __launch_bounds__(256, 3) void k_mma(const __half* __restrict__ Ah,
                                                const __half* __restrict__ Wh,
                                                __half* __restrict__ C) {
    extern __shared__ __align__(16) __half dsm[];
    __half* As = dsm;                       // STAGES * A_ST
    __half* Bs = dsm + STAGES * A_ST;       // STAGES * B_ST
    int tid = threadIdx.x;
    int bm = blockIdx.y * 64, bn = blockIdx.x * 128;
    int warp = tid >> 5, lane = tid & 31;
    int wr = warp >> 2, wc = warp & 3;

    float acc[2][4][4];
#pragma unroll
    for (int i = 0; i < 2; i++)
#pragma unroll
        for (int j = 0; j < 4; j++)
#pragma unroll
            for (int f = 0; f < 4; f++) acc[i][j][f] = 0.f;

    int ar = tid >> 2, ac = (tid & 3) * 8;
    int br = tid >> 4, bc = (tid & 15) * 8;

    uint32_t sA0 = smem_u32(&As[ar * APITCH + ac]);
    uint32_t sB0 = smem_u32(&Bs[br * BPITCH + bc]);
    uint32_t sB1 = smem_u32(&Bs[(br + 16) * BPITCH + bc]);
    uint32_t lA0 = smem_u32(&As[(wr * 32 + (lane & 15)) * APITCH + ((lane >> 4) << 3)]);
    uint32_t lB0 = smem_u32(&Bs[(lane & 15) * BPITCH + wc * 32]);

    const __half* gA = Ah + (size_t)(bm + ar) * DIM + ac;   // + k0
    const __half* gB = Wh + (size_t)br * DIM + bn + bc;     // + k0 * DIM

#define LOAD_TILE(i, slot)                                                   \
    do {                                                                     \
        int k0 = (i) * 32;                                                   \
        const __half* ga = gA + k0;                                          \
        const __half* gb = gB + (size_t)k0 * DIM;                            \
        CP_ASYNC16(sA0 + (slot) * (A_ST * 2), ga);                           \
        CP_ASYNC16(sB0 + (slot) * (B_ST * 2), gb);                           \
        CP_ASYNC16(sB1 + (slot) * (B_ST * 2), gb + 16 * DIM);                \
    } while (0)

    LOAD_TILE(0, 0); CP_COMMIT();
    LOAD_TILE(1, 1); CP_COMMIT();
    LOAD_TILE(2, 2); CP_COMMIT();

    int slot = 0, pslot = 3;
    for (int i = 0; i < NIT; i++) {
        CP_WAIT(2);
        __syncthreads();
        if (i + 3 < NIT) LOAD_TILE(i + 3, pslot);
        CP_COMMIT();
        uint32_t lA = lA0 + slot * (A_ST * 2);
        uint32_t lB = lB0 + slot * (B_ST * 2);
#pragma unroll
        for (int kt = 0; kt < 2; kt++) {
            uint32_t a[2][4];
#pragma unroll
            for (int mt = 0; mt < 2; mt++)
                LDSM4(a[mt][0], a[mt][1], a[mt][2], a[mt][3],
                      lA + (mt * 16 * APITCH + kt * 16) * 2);
            uint32_t b[4][2];
#pragma unroll
            for (int nt = 0; nt < 4; nt++)
                LDSM2T(b[nt][0], b[nt][1], lB + (kt * 16 * BPITCH + nt * 8) * 2);
#pragma unroll
            for (int mt = 0; mt < 2; mt++)
#pragma unroll
                for (int nt = 0; nt < 4; nt++) MMA16816H(acc[mt][nt], a[mt], b[nt]);
        }
        if (++slot == STAGES) slot = 0;
        if (++pslot == STAGES) pslot = 0;
    }

#pragma unroll
    for (int mt = 0; mt < 2; mt++)
#pragma unroll
        for (int nt = 0; nt < 4; nt++) {
            int row = bm + wr * 32 + mt * 16 + (lane >> 2);
            int col = bn + wc * 32 + nt * 8 + (lane & 3) * 2;
            *(__half2*)&C[(size_t)row * DIM + col] =
                __floats2half2_rn(acc[mt][nt][0], acc[mt][nt][1]);
            *(__half2*)&C[(size_t)(row + 8) * DIM + col] =
                __floats2half2_rn(acc[mt][nt][2], acc[mt][nt][3]);
        }
}

// ================= gather core: warp-per-node, lane owns cols [8l, 8l+8), fp16 t =================
__device__ __forceinline__ void gather_node(const __half* __restrict__ t,
                                            const float* __restrict__ bias,
                                            int node, int lane,
                                            float4& a0, float4& a1) {
    a0 = *(const float4*)&bias[8 * lane];
    a1 = *(const float4*)&bias[8 * lane + 4];
    int cnt = min(g_deg[node], CAP);
    const int2* bk = g_bucket + (size_t)node * CAP;
    for (int j0 = 0; j0 < cnt; j0 += 32) {
        int2 e = make_int2(0, 0);
        if (j0 + lane < cnt) e = bk[j0 + lane];
        int m = min(32, cnt - j0);
#pragma unroll 4
        for (int j = 0; j < m; j++) {
            int s = __shfl_sync(0xffffffffu, e.x, j);
            float w = __int_as_float(__shfl_sync(0xffffffffu, e.y, j));
            uint4 v = *(const uint4*)(t + (size_t)s * DIM + 8 * lane);
            float2 f0 = __half22float2(*(__half2*)&v.x);
            float2 f1 = __half22float2(*(__half2*)&v.y);
            float2 f2 = __half22float2(*(__half2*)&v.z);
            float2 f3 = __half22float2(*(__half2*)&v.w);
            a0.x += w * f0.x; a0.y += w * f0.y; a0.z += w * f1.x; a0.w += w * f1.y;
            a1.x += w * f2.x; a1.y += w * f2.y; a1.z += w * f3.x; a1.w += w * f3.y;
        }
    }
    a0.x = fmaxf(a0.x, 0.f); a0.y = fmaxf(a0.y, 0.f);
    a0.z = fmaxf(a0.z, 0.f); a0.w = fmaxf(a0.w, 0.f);
    a1.x = fmaxf(a1.x, 0.f); a1.y = fmaxf(a1.y, 0.f);
    a1.w = fmaxf(a1.w, 0.f); a1.z = fmaxf(a1.z, 0.f);
}

// ================= agg layer 1: gather + relu -> fp16 =================
__global__ __launch_bounds__(256) void k_agg1(const __half* __restrict__ t,
                                              const float* __restrict__ bias,
                                              __half* __restrict__ outh) {
    int warp = threadIdx.x >> 5, lane = threadIdx.x & 31;
    int node = blockIdx.x * 8 + warp;
    float4 a0, a1;
    gather_node(t, bias, node, lane, a0, a1);
    *(uint4*)&outh[(size_t)node * DIM + 8 * lane] =
        make_uint4(h2_pack(a0.x, a0.y), h2_pack(a0.z, a0.w),
                   h2_pack(a1.x, a1.y), h2_pack(a1.z, a1.w));
}

// ================= fused agg2 + MLP + softmax + colsumsq + loss (ticket) =================
__global__ __launch_bounds__(512) void k_aggmlp(const __half* __restrict__ t,
                                                const float* __restrict__ bias,
                                                const float* __restrict__ Wm,
                                                const float* __restrict__ bm,
                                                float* __restrict__ out,
                                                float* __restrict__ out_loss, int Nn) {
    __shared__ float sW[KCL * DIM];
    __shared__ float sh[16][DIM];
    __shared__ float part[16][KCL];
    __shared__ float sbm[KCL];
    int tid = threadIdx.x;
    for (int idx = tid; idx < KCL * DIM; idx += 512)
        sW[idx] = Wm[(idx & 255) * KCL + (idx >> 8)];
    if (tid < KCL) sbm[tid] = bm[tid];

    int warp = tid >> 5, lane = tid & 31;
    int node = blockIdx.x * 16 + warp;
    float4 a0, a1;
    gather_node(t, bias, node, lane, a0, a1);
    *(float4*)&sh[warp][8 * lane] = a0;
    *(float4*)&sh[warp][8 * lane + 4] = a1;
    __syncthreads();

    float acc[KCL];
#pragma unroll
    for (int k = 0; k < KCL; k++) acc[k] = 0.f;
#pragma unroll
    for (int m = 0; m < 8; m++) {
        float hv = sh[warp][lane + 32 * m];
#pragma unroll
        for (int k = 0; k < KCL; k++) acc[k] += hv * sW[k * DIM + lane + 32 * m];
    }
#pragma unroll
    for (int off = 16; off >= 1; off >>= 1)
#pragma unroll
        for (int k = 0; k < KCL; k++) acc[k] += __shfl_xor_sync(0xffffffffu, acc[k], off);

    if (lane < KCL) {
        float logit = acc[lane] + sbm[lane];
        float mx = logit;
#pragma unroll
        for (int off = 8; off >= 1; off >>= 1) mx = fmaxf(mx, __shfl_xor_sync(0xffffu, mx, off));
        float e = expf(logit - mx);
        float se = e;
#pragma unroll
        for (int off = 8; off >= 1; off >>= 1) se += __shfl_xor_sync(0xffffu, se, off);
        float sv = e / se;
        out[(size_t)node * KCL + lane] = sv;
        part[warp][lane] = sv * sv;
    }
    __syncthreads();
    if (tid < KCL) {
        float s = 0.f;
#pragma unroll
        for (int w = 0; w < 16; w++) s += part[w][tid];
        atomicAdd(&g_red[tid], s);
    }
    __syncthreads();
    if (tid == 0) {
        __threadfence();
        int prev = atomicAdd((int*)&g_red[KCL], 1);
        if (prev == (int)gridDim.x - 1) {
            float L = 0.f;
#pragma unroll
            for (int k = 0; k < KCL; k++) L += sqrtf(g_red[k] + 1e-15f);
            *out_loss = -L / sqrtf((float)Nn * (float)KCL);
        }
    }
}

// ================= launch =================
extern "C" void kernel_launch(void* const* d_in, const int* in_sizes, int n_in,
                              void* d_out, int out_size) {
    const float* x  = (const float*)d_in[0];
    const float* ew = (const float*)d_in[1];
    const float* W1 = (const float*)d_in[2];
    const float* b1 = (const float*)d_in[3];
    const float* W2 = (const float*)d_in[4];
    const float* b2 = (const float*)d_in[5];
    const float* Wm = (const float*)d_in[6];
    const float* bm = (const float*)d_in[7];
    const int*   ei = (const int*)d_in[8];

    int Nn = in_sizes[0] / DIM;
    int E  = in_sizes[1];
    const int* src = ei;
    const int* dst = ei + E;
    float* out = (float*)d_out;

    float* red_buf;
    __half *t_buf, *a_buf, *w1_buf, *w2_buf;
    int* deg_buf;
    cudaGetSymbolAddress((void**)&t_buf, g_t);
    cudaGetSymbolAddress((void**)&a_buf, g_a);
    cudaGetSymbolAddress((void**)&w1_buf, g_w1);
    cudaGetSymbolAddress((void**)&w2_buf, g_w2);
    cudaGetSymbolAddress((void**)&deg_buf, g_deg);
    cudaGetSymbolAddress((void**)&red_buf, g_red);

    cudaFuncSetAttribute(k_mma, cudaFuncAttributeMaxDynamicSharedMemorySize, SMEM_MMA);

    cudaMemsetAsync(deg_buf, 0, N_NODES * sizeof(int));
    cudaMemsetAsync(red_buf, 0, (KCL + 1) * sizeof(float));

    int FB = E / 512;
    int CA = (Nn * DIM) / 2048;
    k_mega<<<FB + 64 + CA, 256>>>(src, dst, ew, x, W1, W2, FB);

    dim3 gmma(DIM / 128, Nn / 64);
    k_mma<<<gmma, 256, SMEM_MMA>>>(a_buf, w1_buf, t_buf);
    k_agg1<<<Nn / 8, 256>>>(t_buf, b1, a_buf);
    k_mma<<<gmma, 256, SMEM_MMA>>>(a_buf, w2_buf, t_buf);
    k_aggmlp<<<Nn / 16, 512>>>(t_buf, b2, Wm, bm, out, out + (out_size - 1), Nn);
}